// round 4
// baseline (speedup 1.0000x reference)
#include <cuda_runtime.h>
#include <math.h>

#define BATCH 32
#define PRI   8732
#define NCLS_TOT 81
#define NCLS  80
#define NTASK (BATCH * NCLS)
#define KTOP  200
#define CONF_TH 0.01f
#define NMS_TH  0.45f
#define CAND_MAX 1024
#define CAND2   256
#define NBINS 4096
#define PRE_BITS 0x3F700000u     // 0.9375f: static prefilter, >= coarse cut bin of top-200

// Scratch (__device__ globals; no allocation allowed)
__device__ float4 g_boxes[BATCH * PRI];
__device__ unsigned long long g_cand[(size_t)NTASK * CAND_MAX];   // prefiltered keys per task
__device__ unsigned g_count[NTASK];

// ---------------------------------------------------------------------------
__global__ void decode_kernel(const float4* __restrict__ loc,
                              const float4* __restrict__ priors) {
    int i = blockIdx.x * blockDim.x + threadIdx.x;
    if (i >= BATCH * PRI) return;
    int p = i % PRI;
    float4 l  = loc[i];
    float4 pr = priors[p];
    float cx = pr.x + (l.x * 0.1f) * pr.z;
    float cy = pr.y + (l.y * 0.1f) * pr.w;
    float w  = pr.z * expf(l.z * 0.2f);
    float h  = pr.w * expf(l.w * 0.2f);
    float x1 = cx - w * 0.5f;
    float y1 = cy - h * 0.5f;
    g_boxes[i] = make_float4(x1, y1, x1 + w, y1 + h);
}

// ---------------------------------------------------------------------------
// Zero per-task counters + background-class output slabs.
__global__ void zero_misc_kernel(float* __restrict__ out) {
    int i = blockIdx.x * blockDim.x + threadIdx.x;
    if (i < NTASK) g_count[i] = 0;
    if (i < BATCH * KTOP * 5) {
        int b = i / (KTOP * 5);
        int r = i % (KTOP * 5);
        out[(size_t)b * NCLS_TOT * KTOP * 5 + r] = 0.0f;
    }
}

// ---------------------------------------------------------------------------
// Single coalesced pass over conf: compact keys with value >= 0.9375 into
// per-task candidate lists. Candidate rate ~6.3% -> ~546/task (cap 1024).
__global__ void filter_kernel(const unsigned* __restrict__ conf) {
    int idx = blockIdx.x * blockDim.x + threadIdx.x;
    if (idx >= BATCH * PRI * NCLS_TOT) return;
    unsigned bits = conf[idx];
    if ((int)bits >= (int)PRE_BITS) {      // signed cmp: rejects negatives too
        unsigned c = (unsigned)idx % 81u;
        if (c != 0u) {
            unsigned rp = (unsigned)idx / 81u;
            unsigned p  = rp % (unsigned)PRI;
            unsigned b  = rp / (unsigned)PRI;
            unsigned task = b * NCLS + c - 1u;
            unsigned pos = atomicAdd(&g_count[task], 1u);
            if (pos < CAND_MAX)
                g_cand[(size_t)task * CAND_MAX + pos] =
                    ((unsigned long long)bits << 32) | (unsigned)(~p);
        }
    }
}

// ---------------------------------------------------------------------------
// Inclusive suffix sum over 256 threads (thread t gets sum over threads >= t).
__device__ __forceinline__ unsigned suffix_incl_256(unsigned part, unsigned* warpTot,
                                                    int lane, int wid) {
    unsigned v = part;
    #pragma unroll
    for (int d = 1; d < 32; d <<= 1) {
        unsigned o = __shfl_down_sync(0xFFFFFFFFu, v, d);
        v += (lane < 32 - d) ? o : 0u;
    }
    if (lane == 0) warpTot[wid] = v;     // lane0 holds whole-warp total
    __syncthreads();
    unsigned add = 0;
    #pragma unroll
    for (int q = 0; q < 8; q++) add += (q > wid) ? warpTot[q] : 0u;
    return v + add;
}

// ---------------------------------------------------------------------------
// Per-(b,c): load prefiltered cands -> coarse cut (hist of cands) -> fine cut
// (256-bin) -> compact<=256 -> register bitonic sort -> ballot suppression
// bitmask -> serial greedy scan -> popcount compaction -> write 200x5 slab.
// Fallback (cand underflow/overflow): strided re-read of the conf column.
__global__ void __launch_bounds__(256, 8) nms_kernel(const unsigned* __restrict__ conf,
                                                     float* __restrict__ out) {
    __shared__ unsigned histM[NBINS];                // 16 KB; overlays below
    __shared__ unsigned long long buf[CAND_MAX];     // 8 KB; cands, then mask
    __shared__ unsigned warpTot[8];
    __shared__ unsigned long long sKeepW[4];
    __shared__ unsigned s_binT, s_above, s_fcut, s_n2, s_gc;
    __shared__ int s_found;

    unsigned long long* cand2 = (unsigned long long*)histM;     // [0..512) u32
    float4* sBox  = (float4*)(histM + 512);                     // 3.2 KB
    float*  sScore = (float*)(histM + 512 + 800);               // 0.8 KB
    unsigned* maskW = (unsigned*)buf;                           // [KTOP][8] u32

    const int task = blockIdx.x;
    const int b    = task / NCLS;
    const int cc   = task % NCLS;
    const int tid  = threadIdx.x;
    const int wid  = tid >> 5;
    const int lane = tid & 31;

    for (int t = tid; t < NBINS; t += 256) histM[t] = 0;
    if (tid == 0) { s_found = 0; s_binT = 0; s_above = 0; s_n2 = 0; s_fcut = 0; s_gc = 0; }
    __syncthreads();

    const unsigned gc0 = g_count[task];
    const bool fast = (gc0 >= KTOP && gc0 <= CAND_MAX);
    int gcount = 0;

    if (fast) {
        gcount = (int)gc0;
        const unsigned long long* src = g_cand + (size_t)task * CAND_MAX;
        for (int t = tid; t < gcount; t += 256) {
            unsigned long long key = src[t];
            buf[t] = key;
            atomicAdd(&histM[(unsigned)(key >> 52)], 1u);
        }
        __syncthreads();
    } else {
        // fallback: full histogram from the (strided) conf column
        const unsigned* col = conf + (size_t)b * PRI * NCLS_TOT + (cc + 1);
        for (int p = tid; p < PRI; p += 256) {
            unsigned bits = col[(size_t)p * NCLS_TOT];
            if (__uint_as_float(bits) > CONF_TH) atomicAdd(&histM[bits >> 20], 1u);
        }
        __syncthreads();
    }

    // ---- coarse cut-find: 16 bins/thread -> suffix scan -> winner refines ----
    {
        unsigned part = 0;
        #pragma unroll
        for (int r = 0; r < 16; r++) part += histM[tid * 16 + r];
        unsigned incl = suffix_incl_256(part, warpTot, lane, wid);
        unsigned excl = incl - part;
        if (excl < KTOP && incl >= KTOP) {       // unique winner thread
            unsigned cum = excl;
            for (int bb = tid * 16 + 15; bb >= tid * 16; bb--) {
                cum += histM[bb];
                if (cum >= KTOP) {
                    s_binT = (unsigned)bb; s_above = cum - histM[bb]; s_found = 1;
                    break;
                }
            }
        }
        __syncthreads();
    }
    const int found = s_found;
    const unsigned binT = s_binT;

    if (!fast) {
        // fallback gather (binT filter; found==0 -> binT==0 -> all positives)
        const unsigned* col = conf + (size_t)b * PRI * NCLS_TOT + (cc + 1);
        for (int p = tid; p < PRI; p += 256) {
            unsigned bits = col[(size_t)p * NCLS_TOT];
            if (__uint_as_float(bits) > CONF_TH && (bits >> 20) >= binT) {
                unsigned pos = atomicAdd(&s_gc, 1u);
                if (pos < CAND_MAX)
                    buf[pos] = ((unsigned long long)bits << 32) | (unsigned)(~(unsigned)p);
            }
        }
        __syncthreads();
        gcount = (int)min(s_gc, (unsigned)CAND_MAX);
    }

    // ---- fine refinement: 256 bins over bits 19..12 within the cut bin ----
    unsigned fcut = 0;
    if (found) {
        histM[tid] = 0;                      // fine hist occupies histM[0..256)
        __syncthreads();
        for (int t = tid; t < gcount; t += 256) {
            unsigned long long key = buf[t];
            if ((unsigned)(key >> 52) == binT)
                atomicAdd(&histM[(unsigned)(key >> 44) & 0xFFu], 1u);
        }
        __syncthreads();
        unsigned part = histM[tid];
        unsigned incl = suffix_incl_256(part, warpTot, lane, wid);
        unsigned excl = incl - part;
        const unsigned need = KTOP - s_above;
        if (excl < need && incl >= need) s_fcut = (unsigned)tid;
        __syncthreads();
        fcut = s_fcut;
        __syncthreads();
    }

    // ---- compact refined candidates into cand2 (overlays histM) ----
    cand2[tid] = 0ULL;
    __syncthreads();
    for (int t = tid; t < gcount; t += 256) {
        unsigned long long key = buf[t];
        unsigned cb = (unsigned)(key >> 52);
        if (cb > binT || (cb == binT && ((unsigned)(key >> 44) & 0xFFu) >= fcut)) {
            unsigned pos = atomicAdd(&s_n2, 1u);
            if (pos < CAND2) cand2[pos] = key;
        }
    }
    __syncthreads();
    const int n = min((int)min(s_n2, (unsigned)CAND2), KTOP);

    // ---- register bitonic sort of 256 keys (asc); shfl intra-warp ----
    unsigned long long key = cand2[tid];
    for (int kk = 2; kk <= 256; kk <<= 1) {
        bool up = ((tid & kk) == 0);
        for (int jj = kk >> 1; jj > 0; jj >>= 1) {
            unsigned long long partner;
            if (jj >= 32) {
                __syncthreads();
                cand2[tid] = key;
                __syncthreads();
                partner = cand2[tid ^ jj];
            } else {
                partner = __shfl_xor_sync(0xFFFFFFFFu, key, jj);
            }
            bool takeMin = (((tid & jj) == 0) == up);
            bool sw = takeMin ? (partner < key) : (partner > key);
            if (sw) key = partner;
        }
    }
    __syncthreads();                 // cand2 reads done; sBox/sScore overlay safe

    // ---- extract top-n (descending) ; zero ballot mask (overlays buf) ----
    {
        int k = 255 - tid;           // descending rank
        if (k < n) {
            unsigned bits = (unsigned)(key >> 32);
            int p = (int)(~(unsigned)key);
            float4 bx = g_boxes[b * PRI + p];
            sBox[k]   = bx;
            sScore[k] = __uint_as_float(bits);
        }
        for (int t = tid; t < KTOP * 8; t += 256) maskW[t] = 0u;
    }
    __syncthreads();

    // ---- suppression bitmask via ballot: rows over warps, no atomics ----
    const int wEnd = (n + 31) >> 5;
    for (int i = wid; i < n; i += 8) {
        float4 bi = sBox[i];
        float  ai = (bi.z - bi.x) * (bi.w - bi.y);
        for (int w = (i + 1) >> 5; w < wEnd; w++) {
            int j = w * 32 + lane;
            bool sup = false;
            if (j > i && j < n) {
                float4 bj = sBox[j];
                float aj = (bj.z - bj.x) * (bj.w - bj.y);
                float ww = fminf(bi.z, bj.z) - fmaxf(bi.x, bj.x);
                float hh = fminf(bi.w, bj.w) - fmaxf(bi.y, bj.y);
                ww = fmaxf(ww, 0.0f); hh = fmaxf(hh, 0.0f);
                float inter = ww * hh;
                sup = inter > NMS_TH * (ai + aj - inter);
            }
            unsigned bal = __ballot_sync(0xFFFFFFFFu, sup);
            if (lane == 0) maskW[i * 8 + w] = bal;
        }
    }
    __syncthreads();

    // ---- serial greedy scan over 4x64-bit keep words ----
    if (tid == 0) {
        const unsigned long long* m64 = (const unsigned long long*)maskW;
        unsigned long long kw[4];
        #pragma unroll
        for (int q = 0; q < 4; q++) {
            int rem = n - q * 64;
            kw[q] = (rem >= 64) ? ~0ULL : (rem > 0 ? ((1ULL << rem) - 1ULL) : 0ULL);
        }
        for (int i = 0; i < n; i++) {
            if ((kw[i >> 6] >> (i & 63)) & 1ULL) {
                kw[0] &= ~m64[i * 4 + 0]; kw[1] &= ~m64[i * 4 + 1];
                kw[2] &= ~m64[i * 4 + 2]; kw[3] &= ~m64[i * 4 + 3];
            }
        }
        sKeepW[0] = kw[0]; sKeepW[1] = kw[1]; sKeepW[2] = kw[2]; sKeepW[3] = kw[3];
    }
    __syncthreads();

    // ---- write slab: vector-zero 200x5, scatter kept rows to front ----
    float* outBase = out + (size_t)(b * NCLS_TOT + cc + 1) * KTOP * 5;
    float4* outBase4 = (float4*)outBase;
    for (int t = tid; t < KTOP * 5 / 4; t += 256)
        outBase4[t] = make_float4(0.f, 0.f, 0.f, 0.f);
    __syncthreads();

    for (int k = tid; k < n; k += 256) {
        unsigned long long w = sKeepW[k >> 6];
        if ((w >> (k & 63)) & 1ULL) {
            int d = 0;
            for (int q = 0; q < (k >> 6); q++) d += __popcll(sKeepW[q]);
            unsigned long long below = (k & 63) ? (w & ((1ULL << (k & 63)) - 1ULL)) : 0ULL;
            d += __popcll(below);
            float* r = outBase + d * 5;
            float4 bx = sBox[k];
            r[0] = sScore[k];
            r[1] = bx.x; r[2] = bx.y; r[3] = bx.z; r[4] = bx.w;
        }
    }
}

// ---------------------------------------------------------------------------
extern "C" void kernel_launch(void* const* d_in, const int* in_sizes, int n_in,
                              void* d_out, int out_size) {
    const float4*   loc   = (const float4*)d_in[0];     // [B, P, 4]
    const unsigned* conf  = (const unsigned*)d_in[1];   // [B*P, C] (float bits)
    const float4*   prior = (const float4*)d_in[2];     // [P, 4]
    float* out = (float*)d_out;                         // [B, C, K, 5]

    decode_kernel<<<(BATCH * PRI + 255) / 256, 256>>>(loc, prior);
    zero_misc_kernel<<<(BATCH * KTOP * 5 + 255) / 256, 256>>>(out);

    int total = BATCH * PRI * NCLS_TOT;
    filter_kernel<<<(total + 255) / 256, 256>>>(conf);

    nms_kernel<<<NTASK, 256>>>(conf, out);
}

// round 5
// speedup vs baseline: 2.5154x; 2.5154x over previous
#include <cuda_runtime.h>
#include <math.h>

#define BATCH 32
#define PRI   8732
#define NCLS_TOT 81
#define NCLS  80
#define NTASK (BATCH * NCLS)
#define KTOP  200
#define CONF_TH 0.01f
#define NMS_TH  0.45f
#define CAND_MAX 1024
#define CAND2   256
#define NBINS 4096
#define PRE_BITS 0x3F700000u     // 0.9375f static prefilter (~546 cands/task, 15 sigma > K)
#define ONE_BITS 0x3F800000u     // 1.0f : fast path requires all cands < 1.0
#define NP_CHUNK 380             // priors per filter block (23 chunks * 380 >= 8732)
#define NCHUNK 23
#define FCAP 64                  // smem staging capacity per class per filter block

// Scratch (__device__ globals; no allocation allowed)
__device__ float4 g_boxes[BATCH * PRI];
__device__ unsigned long long g_cand[(size_t)NTASK * CAND_MAX];
__device__ unsigned g_count[NTASK];

// ---------------------------------------------------------------------------
__global__ void decode_kernel(const float4* __restrict__ loc,
                              const float4* __restrict__ priors) {
    int i = blockIdx.x * blockDim.x + threadIdx.x;
    if (i >= BATCH * PRI) return;
    int p = i % PRI;
    float4 l  = loc[i];
    float4 pr = priors[p];
    float cx = pr.x + (l.x * 0.1f) * pr.z;
    float cy = pr.y + (l.y * 0.1f) * pr.w;
    float w  = pr.z * expf(l.z * 0.2f);
    float h  = pr.w * expf(l.w * 0.2f);
    float x1 = cx - w * 0.5f;
    float y1 = cy - h * 0.5f;
    g_boxes[i] = make_float4(x1, y1, x1 + w, y1 + h);
}

// ---------------------------------------------------------------------------
__global__ void zero_misc_kernel(float* __restrict__ out) {
    int i = blockIdx.x * blockDim.x + threadIdx.x;
    if (i < NTASK) g_count[i] = 0;
    if (i < BATCH * KTOP * 5) {
        int b = i / (KTOP * 5);
        int r = i % (KTOP * 5);
        out[(size_t)b * NCLS_TOT * KTOP * 5 + r] = 0.0f;
    }
}

// ---------------------------------------------------------------------------
// SMEM-staged filter: one coalesced pass over conf; candidates staged in
// per-class smem lists; ONE global atomicAdd per (class, block) at drain.
// ---------------------------------------------------------------------------
__global__ void __launch_bounds__(256) filter_kernel(const unsigned* __restrict__ conf) {
    __shared__ unsigned long long stage[NCLS * FCAP];   // 40 KB
    __shared__ unsigned scount[NCLS];

    const int chunk = blockIdx.x;          // 0..22
    const int b     = blockIdx.y;          // 0..31
    const int p0    = chunk * NP_CHUNK;
    const int tid   = threadIdx.x;
    const int lane  = tid & 31;
    const int wid   = tid >> 5;

    for (int t = tid; t < NCLS; t += 256) scount[t] = 0;
    __syncthreads();

    const int np    = min(NP_CHUNK, PRI - p0);
    const int limit = np * NCLS_TOT;
    const unsigned* base = conf + ((size_t)b * PRI + p0) * NCLS_TOT;

    int c = tid % NCLS_TOT;
    int p = p0 + tid / NCLS_TOT;
    for (int e = tid; e < limit; e += 256) {
        unsigned bits = base[e];
        if ((int)bits >= (int)PRE_BITS && c != 0) {
            int cls = c - 1;
            unsigned long long key =
                ((unsigned long long)bits << 32) | (unsigned)(~(unsigned)p);
            unsigned pos = atomicAdd(&scount[cls], 1u);
            if (pos < FCAP) {
                stage[cls * FCAP + pos] = key;
            } else {
                int task = b * NCLS + cls;
                unsigned g = atomicAdd(&g_count[task], 1u);
                if (g < CAND_MAX) g_cand[(size_t)task * CAND_MAX + g] = key;
            }
        }
        c += 13; p += 3;                 // advance by 256 = 3*81 + 13
        if (c >= NCLS_TOT) { c -= NCLS_TOT; p += 1; }
    }
    __syncthreads();

    // drain: one warp per class (round-robin), bulk reserve + coalesced copy
    for (int cls = wid; cls < NCLS; cls += 8) {
        unsigned cnt = min(scount[cls], (unsigned)FCAP);
        if (cnt == 0) continue;
        int task = b * NCLS + cls;
        unsigned bse = 0;
        if (lane == 0) bse = atomicAdd(&g_count[task], cnt);
        bse = __shfl_sync(0xFFFFFFFFu, bse, 0);
        for (unsigned t = lane; t < cnt; t += 32) {
            unsigned pos = bse + t;
            if (pos < CAND_MAX)
                g_cand[(size_t)task * CAND_MAX + pos] = stage[cls * FCAP + t];
        }
    }
}

// ---------------------------------------------------------------------------
__device__ __forceinline__ unsigned suffix_incl_256(unsigned part, unsigned* warpTot,
                                                    int lane, int wid) {
    unsigned v = part;
    #pragma unroll
    for (int d = 1; d < 32; d <<= 1) {
        unsigned o = __shfl_down_sync(0xFFFFFFFFu, v, d);
        v += (lane < 32 - d) ? o : 0u;
    }
    if (lane == 0) warpTot[wid] = v;
    __syncthreads();
    unsigned add = 0;
    #pragma unroll
    for (int q = 0; q < 8; q++) add += (q > wid) ? warpTot[q] : 0u;
    return v + add;
}

// ---------------------------------------------------------------------------
// Per-(b,c): cands from g_cand (fast) or column re-read (fallback) -> fine cut
// (bits 19:12) -> optional fine2 (bits 11:4) -> compact<=256 -> register
// bitonic sort -> ballot suppression mask -> serial greedy -> compact output.
// ---------------------------------------------------------------------------
__global__ void __launch_bounds__(256, 8) nms_kernel(const unsigned* __restrict__ conf,
                                                     float* __restrict__ out) {
    __shared__ unsigned histM[NBINS];                // fast path uses [0..256) only
    __shared__ unsigned long long buf[CAND_MAX];     // cands, later ballot mask
    __shared__ unsigned warpTot[8];
    __shared__ unsigned long long sKeepW[4];
    __shared__ unsigned s_binT, s_above, s_fcut, s_aboveF, s_cntF, s_f2cut, s_n2, s_gc, s_bad;
    __shared__ int s_found;

    unsigned long long* cand2 = (unsigned long long*)histM;     // 2 KB
    float4* sBox   = (float4*)(histM + 512);                    // 3.2 KB
    float*  sScore = (float*)(histM + 512 + 800);               // 0.8 KB
    unsigned* maskW = (unsigned*)buf;                           // [KTOP][8] u32

    const int task = blockIdx.x;
    const int b    = task / NCLS;
    const int cc   = task % NCLS;
    const int tid  = threadIdx.x;
    const int wid  = tid >> 5;
    const int lane = tid & 31;

    if (tid == 0) {
        s_found = 0; s_binT = 0; s_above = 0; s_fcut = 0;
        s_aboveF = 0; s_cntF = 0; s_f2cut = 0; s_n2 = 0; s_gc = 0; s_bad = 0;
    }
    __syncthreads();

    const unsigned gc0 = g_count[task];
    const bool fastCnt = (gc0 >= KTOP && gc0 <= CAND_MAX);
    int gcount = 0;

    if (fastCnt) {
        const unsigned long long* src = g_cand + (size_t)task * CAND_MAX;
        unsigned bad = 0;
        for (int t = tid; t < (int)gc0; t += 256) {
            unsigned long long key = src[t];
            buf[t] = key;
            bad |= ((unsigned)(key >> 32) >= ONE_BITS) ? 1u : 0u;
        }
        if (__any_sync(0xFFFFFFFFu, bad) && lane == 0) atomicOr(&s_bad, 1u);
    }
    __syncthreads();
    const bool fast = fastCnt && (s_bad == 0);

    if (fast) {
        // all candidate bits in [0x3F700000, 0x3F800000) -> single coarse bin
        if (tid == 0) { s_binT = PRE_BITS >> 20; s_above = 0; s_found = 1; }
        gcount = (int)gc0;
        histM[tid] = 0;                   // fine hist region only
        __syncthreads();
    } else {
        // fallback: full coarse histogram from the strided conf column
        for (int t = tid; t < NBINS; t += 256) histM[t] = 0;
        __syncthreads();
        const unsigned* col = conf + (size_t)b * PRI * NCLS_TOT + (cc + 1);
        for (int p = tid; p < PRI; p += 256) {
            unsigned bits = col[(size_t)p * NCLS_TOT];
            if (__uint_as_float(bits) > CONF_TH) atomicAdd(&histM[bits >> 20], 1u);
        }
        __syncthreads();
        unsigned part = 0;
        #pragma unroll
        for (int r = 0; r < 16; r++) part += histM[tid * 16 + r];
        unsigned incl = suffix_incl_256(part, warpTot, lane, wid);
        unsigned excl = incl - part;
        if (excl < KTOP && incl >= KTOP) {
            unsigned cum = excl;
            for (int bb = tid * 16 + 15; bb >= tid * 16; bb--) {
                cum += histM[bb];
                if (cum >= KTOP) {
                    s_binT = (unsigned)bb; s_above = cum - histM[bb]; s_found = 1;
                    break;
                }
            }
        }
        __syncthreads();
        const unsigned bT = s_binT;
        for (int p = tid; p < PRI; p += 256) {
            unsigned bits = col[(size_t)p * NCLS_TOT];
            if (__uint_as_float(bits) > CONF_TH && (bits >> 20) >= bT) {
                unsigned pos = atomicAdd(&s_gc, 1u);
                if (pos < CAND_MAX)
                    buf[pos] = ((unsigned long long)bits << 32) | (unsigned)(~(unsigned)p);
            }
        }
        __syncthreads();
        gcount = (int)min(s_gc, (unsigned)CAND_MAX);
        histM[tid] = 0;                   // prep fine hist
        __syncthreads();
    }

    const int found = s_found;
    const unsigned binT = s_binT;
    const unsigned need = KTOP - s_above;

    // ---- fine refinement: 256 bins over bits[19:12] within the cut bin ----
    if (found) {
        for (int t = tid; t < gcount; t += 256) {
            unsigned long long key = buf[t];
            if ((unsigned)(key >> 52) == binT)
                atomicAdd(&histM[(unsigned)(key >> 44) & 0xFFu], 1u);
        }
        __syncthreads();
        unsigned part = histM[tid];
        unsigned incl = suffix_incl_256(part, warpTot, lane, wid);
        unsigned excl = incl - part;
        if (excl < need && incl >= need) {
            s_fcut = (unsigned)tid; s_aboveF = excl; s_cntF = part;
        }
        __syncthreads();
    }
    const unsigned fcut = s_fcut;

    // ---- optional fine2 on bits[11:4] (only if cut bin would overflow sort) ----
    if (found && (s_aboveF + s_cntF > CAND2)) {
        const unsigned need2 = need - s_aboveF;
        histM[tid] = 0;
        __syncthreads();
        for (int t = tid; t < gcount; t += 256) {
            unsigned long long key = buf[t];
            if ((unsigned)(key >> 52) == binT &&
                ((unsigned)(key >> 44) & 0xFFu) == fcut)
                atomicAdd(&histM[(unsigned)(key >> 36) & 0xFFu], 1u);
        }
        __syncthreads();
        unsigned part = histM[tid];
        unsigned incl = suffix_incl_256(part, warpTot, lane, wid);
        unsigned excl = incl - part;
        if (excl < need2 && incl >= need2) s_f2cut = (unsigned)tid;
        __syncthreads();
    }
    const unsigned f2cut = s_f2cut;
    __syncthreads();                      // histM free before cand2 overlay

    // ---- compact refined candidates into cand2 ----
    cand2[tid] = 0ULL;
    __syncthreads();
    for (int t = tid; t < gcount; t += 256) {
        unsigned long long key = buf[t];
        unsigned cb = (unsigned)(key >> 52);
        unsigned fb = (unsigned)(key >> 44) & 0xFFu;
        unsigned f2 = (unsigned)(key >> 36) & 0xFFu;
        if (cb > binT ||
            (cb == binT && (fb > fcut || (fb == fcut && f2 >= f2cut)))) {
            unsigned pos = atomicAdd(&s_n2, 1u);
            if (pos < CAND2) cand2[pos] = key;
        }
    }
    __syncthreads();
    const int n = min((int)min(s_n2, (unsigned)CAND2), KTOP);

    // ---- register bitonic sort of 256 keys (asc) ----
    unsigned long long key = cand2[tid];
    for (int kk = 2; kk <= 256; kk <<= 1) {
        bool up = ((tid & kk) == 0);
        for (int jj = kk >> 1; jj > 0; jj >>= 1) {
            unsigned long long partner;
            if (jj >= 32) {
                __syncthreads();
                cand2[tid] = key;
                __syncthreads();
                partner = cand2[tid ^ jj];
            } else {
                partner = __shfl_xor_sync(0xFFFFFFFFu, key, jj);
            }
            bool takeMin = (((tid & jj) == 0) == up);
            bool sw = takeMin ? (partner < key) : (partner > key);
            if (sw) key = partner;
        }
    }
    __syncthreads();

    // ---- extract top-n (descending) ; zero ballot mask ----
    {
        int k = 255 - tid;
        if (k < n) {
            unsigned bits = (unsigned)(key >> 32);
            int p = (int)(~(unsigned)key);
            float4 bx = g_boxes[b * PRI + p];
            sBox[k]   = bx;
            sScore[k] = __uint_as_float(bits);
        }
        for (int t = tid; t < KTOP * 8; t += 256) maskW[t] = 0u;
    }
    __syncthreads();

    // ---- suppression bitmask via ballot ----
    const int wEnd = (n + 31) >> 5;
    for (int i = wid; i < n; i += 8) {
        float4 bi = sBox[i];
        float  ai = (bi.z - bi.x) * (bi.w - bi.y);
        for (int w = (i + 1) >> 5; w < wEnd; w++) {
            int j = w * 32 + lane;
            bool sup = false;
            if (j > i && j < n) {
                float4 bj = sBox[j];
                float aj = (bj.z - bj.x) * (bj.w - bj.y);
                float ww = fminf(bi.z, bj.z) - fmaxf(bi.x, bj.x);
                float hh = fminf(bi.w, bj.w) - fmaxf(bi.y, bj.y);
                ww = fmaxf(ww, 0.0f); hh = fmaxf(hh, 0.0f);
                float inter = ww * hh;
                sup = inter > NMS_TH * (ai + aj - inter);
            }
            unsigned bal = __ballot_sync(0xFFFFFFFFu, sup);
            if (lane == 0) maskW[i * 8 + w] = bal;
        }
    }
    __syncthreads();

    // ---- serial greedy scan ----
    if (tid == 0) {
        const unsigned long long* m64 = (const unsigned long long*)maskW;
        unsigned long long kw[4];
        #pragma unroll
        for (int q = 0; q < 4; q++) {
            int rem = n - q * 64;
            kw[q] = (rem >= 64) ? ~0ULL : (rem > 0 ? ((1ULL << rem) - 1ULL) : 0ULL);
        }
        for (int i = 0; i < n; i++) {
            if ((kw[i >> 6] >> (i & 63)) & 1ULL) {
                kw[0] &= ~m64[i * 4 + 0]; kw[1] &= ~m64[i * 4 + 1];
                kw[2] &= ~m64[i * 4 + 2]; kw[3] &= ~m64[i * 4 + 3];
            }
        }
        sKeepW[0] = kw[0]; sKeepW[1] = kw[1]; sKeepW[2] = kw[2]; sKeepW[3] = kw[3];
    }
    __syncthreads();

    // ---- write slab ----
    float* outBase = out + (size_t)(b * NCLS_TOT + cc + 1) * KTOP * 5;
    float4* outBase4 = (float4*)outBase;
    for (int t = tid; t < KTOP * 5 / 4; t += 256)
        outBase4[t] = make_float4(0.f, 0.f, 0.f, 0.f);
    __syncthreads();

    for (int k = tid; k < n; k += 256) {
        unsigned long long w = sKeepW[k >> 6];
        if ((w >> (k & 63)) & 1ULL) {
            int d = 0;
            for (int q = 0; q < (k >> 6); q++) d += __popcll(sKeepW[q]);
            unsigned long long below = (k & 63) ? (w & ((1ULL << (k & 63)) - 1ULL)) : 0ULL;
            d += __popcll(below);
            float* r = outBase + d * 5;
            float4 bx = sBox[k];
            r[0] = sScore[k];
            r[1] = bx.x; r[2] = bx.y; r[3] = bx.z; r[4] = bx.w;
        }
    }
}

// ---------------------------------------------------------------------------
extern "C" void kernel_launch(void* const* d_in, const int* in_sizes, int n_in,
                              void* d_out, int out_size) {
    const float4*   loc   = (const float4*)d_in[0];     // [B, P, 4]
    const unsigned* conf  = (const unsigned*)d_in[1];   // [B*P, C] (float bits)
    const float4*   prior = (const float4*)d_in[2];     // [P, 4]
    float* out = (float*)d_out;                         // [B, C, K, 5]

    decode_kernel<<<(BATCH * PRI + 255) / 256, 256>>>(loc, prior);
    zero_misc_kernel<<<(BATCH * KTOP * 5 + 255) / 256, 256>>>(out);

    dim3 fg(NCHUNK, BATCH);
    filter_kernel<<<fg, 256>>>(conf);

    nms_kernel<<<NTASK, 256>>>(conf, out);
}

// round 6
// speedup vs baseline: 3.0505x; 1.2127x over previous
#include <cuda_runtime.h>
#include <math.h>

#define BATCH 32
#define PRI   8732
#define NCLS_TOT 81
#define NCLS  80
#define NTASK (BATCH * NCLS)
#define KTOP  200
#define CONF_TH 0.01f
#define NMS_TH  0.45f
#define CAND_MAX 1024
#define CAND2   256
#define NBINS 4096
#define PRE_BITS 0x3F780000u     // 0.96875f prefilter: ~273 cands/task (4.5 sigma > K=200)
#define ONE_BITS 0x3F800000u
#define NP_CHUNK 380             // priors per filter block (23 * 380 >= 8732)
#define NCHUNK 23
#define FCAP 32                  // smem staging per class per filter block (mean ~12)

// Scratch (__device__ globals; no allocation allowed)
__device__ float4 g_boxes[BATCH * PRI];
__device__ unsigned long long g_cand[(size_t)NTASK * CAND_MAX];
__device__ unsigned g_count[NTASK];

// ---------------------------------------------------------------------------
__global__ void decode_kernel(const float4* __restrict__ loc,
                              const float4* __restrict__ priors) {
    int i = blockIdx.x * blockDim.x + threadIdx.x;
    if (i >= BATCH * PRI) return;
    int p = i % PRI;
    float4 l  = loc[i];
    float4 pr = priors[p];
    float cx = pr.x + (l.x * 0.1f) * pr.z;
    float cy = pr.y + (l.y * 0.1f) * pr.w;
    float w  = pr.z * expf(l.z * 0.2f);
    float h  = pr.w * expf(l.w * 0.2f);
    float x1 = cx - w * 0.5f;
    float y1 = cy - h * 0.5f;
    g_boxes[i] = make_float4(x1, y1, x1 + w, y1 + h);
}

// ---------------------------------------------------------------------------
__global__ void zero_misc_kernel(float* __restrict__ out) {
    int i = blockIdx.x * blockDim.x + threadIdx.x;
    if (i < NTASK) g_count[i] = 0;
    if (i < BATCH * KTOP * 5) {
        int b = i / (KTOP * 5);
        int r = i % (KTOP * 5);
        out[(size_t)b * NCLS_TOT * KTOP * 5 + r] = 0.0f;
    }
}

// ---------------------------------------------------------------------------
// Vectorized SMEM-staged filter: uint4 pass over conf; class/prior derived
// only for passing elements (~3%); one global atomicAdd per (class, block).
// ---------------------------------------------------------------------------
__global__ void __launch_bounds__(256) filter_kernel(const unsigned* __restrict__ conf) {
    __shared__ unsigned long long stage[NCLS * FCAP];   // 20 KB
    __shared__ unsigned scount[NCLS];

    const int chunk = blockIdx.x;
    const int b     = blockIdx.y;
    const int p0    = chunk * NP_CHUNK;
    const int tid   = threadIdx.x;
    const int lane  = tid & 31;
    const int wid   = tid >> 5;

    for (int t = tid; t < NCLS; t += 256) scount[t] = 0;
    __syncthreads();

    const int np     = min(NP_CHUNK, PRI - p0);
    const int limit4 = (np * NCLS_TOT) >> 2;           // always divisible by 4
    const uint4* base4 = (const uint4*)(conf + ((size_t)b * PRI + p0) * NCLS_TOT);

    for (int e4 = tid; e4 < limit4; e4 += 256) {
        uint4 v = base4[e4];
        #pragma unroll
        for (int k = 0; k < 4; k++) {
            unsigned bits = (k == 0) ? v.x : (k == 1) ? v.y : (k == 2) ? v.z : v.w;
            if ((int)bits >= (int)PRE_BITS) {
                unsigned eloc = (unsigned)(e4 << 2) + k;
                unsigned row  = eloc / NCLS_TOT;       // mul-shift by ptxas
                unsigned c    = eloc - row * NCLS_TOT;
                if (c != 0u) {
                    unsigned p = (unsigned)p0 + row;
                    int cls = (int)c - 1;
                    unsigned long long key =
                        ((unsigned long long)bits << 32) | (unsigned)(~p);
                    unsigned pos = atomicAdd(&scount[cls], 1u);
                    if (pos < FCAP) {
                        stage[cls * FCAP + pos] = key;
                    } else {
                        int task = b * NCLS + cls;
                        unsigned g = atomicAdd(&g_count[task], 1u);
                        if (g < CAND_MAX) g_cand[(size_t)task * CAND_MAX + g] = key;
                    }
                }
            }
        }
    }
    __syncthreads();

    for (int cls = wid; cls < NCLS; cls += 8) {
        unsigned cnt = min(scount[cls], (unsigned)FCAP);
        if (cnt == 0) continue;
        int task = b * NCLS + cls;
        unsigned bse = 0;
        if (lane == 0) bse = atomicAdd(&g_count[task], cnt);
        bse = __shfl_sync(0xFFFFFFFFu, bse, 0);
        if (lane < cnt) {
            unsigned pos = bse + lane;
            if (pos < CAND_MAX)
                g_cand[(size_t)task * CAND_MAX + pos] = stage[cls * FCAP + lane];
        }
    }
}

// ---------------------------------------------------------------------------
__device__ __forceinline__ unsigned suffix_incl_256(unsigned part, unsigned* warpTot,
                                                    int lane, int wid) {
    unsigned v = part;
    #pragma unroll
    for (int d = 1; d < 32; d <<= 1) {
        unsigned o = __shfl_down_sync(0xFFFFFFFFu, v, d);
        v += (lane < 32 - d) ? o : 0u;
    }
    if (lane == 0) warpTot[wid] = v;
    __syncthreads();
    unsigned add = 0;
    #pragma unroll
    for (int q = 0; q < 8; q++) add += (q > wid) ? warpTot[q] : 0u;
    return v + add;
}

// ---------------------------------------------------------------------------
__global__ void __launch_bounds__(256, 8) nms_kernel(const unsigned* __restrict__ conf,
                                                     float* __restrict__ out) {
    __shared__ unsigned histM[NBINS];                // fast path: [0..256) only
    __shared__ unsigned long long buf[CAND_MAX];     // cands, later ballot mask
    __shared__ unsigned warpTot[8];
    __shared__ unsigned long long sKeepW[4];
    __shared__ unsigned s_binT, s_above, s_fcut, s_aboveF, s_cntF, s_f2cut, s_n2, s_gc, s_bad;
    __shared__ int s_found;

    unsigned long long* cand2 = (unsigned long long*)histM;     // u32 [0..512)
    float4* sBox   = (float4*)(histM + 512);                    // [512..1312)
    float*  sScore = (float*)(histM + 1312);                    // [1312..1512)
    float*  sTArea = (float*)(histM + 1512);                    // [1512..1712): T*area
    unsigned* maskW = (unsigned*)buf;                           // [KTOP][8] u32

    const int task = blockIdx.x;
    const int b    = task / NCLS;
    const int cc   = task % NCLS;
    const int tid  = threadIdx.x;
    const int wid  = tid >> 5;
    const int lane = tid & 31;

    if (tid == 0) {
        s_found = 0; s_binT = 0; s_above = 0; s_fcut = 0;
        s_aboveF = 0; s_cntF = 0; s_f2cut = 0; s_n2 = 0; s_gc = 0; s_bad = 0;
    }
    __syncthreads();

    const unsigned gc0 = g_count[task];
    const bool fastCnt = (gc0 >= KTOP && gc0 <= CAND_MAX);
    int gcount = 0;

    if (fastCnt) {
        const unsigned long long* src = g_cand + (size_t)task * CAND_MAX;
        unsigned bad = 0;
        for (int t = tid; t < (int)gc0; t += 256) {
            unsigned long long key = src[t];
            buf[t] = key;
            bad |= ((unsigned)(key >> 32) >= ONE_BITS) ? 1u : 0u;
        }
        if (__any_sync(0xFFFFFFFFu, bad) && lane == 0) atomicOr(&s_bad, 1u);
    }
    __syncthreads();
    const bool fast = fastCnt && (s_bad == 0);

    if (fast) {
        if (tid == 0) { s_binT = PRE_BITS >> 20; s_above = 0; s_found = 1; }
        gcount = (int)gc0;
        histM[tid] = 0;
        __syncthreads();
    } else {
        for (int t = tid; t < NBINS; t += 256) histM[t] = 0;
        __syncthreads();
        const unsigned* col = conf + (size_t)b * PRI * NCLS_TOT + (cc + 1);
        for (int p = tid; p < PRI; p += 256) {
            unsigned bits = col[(size_t)p * NCLS_TOT];
            if (__uint_as_float(bits) > CONF_TH) atomicAdd(&histM[bits >> 20], 1u);
        }
        __syncthreads();
        unsigned part = 0;
        #pragma unroll
        for (int r = 0; r < 16; r++) part += histM[tid * 16 + r];
        unsigned incl = suffix_incl_256(part, warpTot, lane, wid);
        unsigned excl = incl - part;
        if (excl < KTOP && incl >= KTOP) {
            unsigned cum = excl;
            for (int bb = tid * 16 + 15; bb >= tid * 16; bb--) {
                cum += histM[bb];
                if (cum >= KTOP) {
                    s_binT = (unsigned)bb; s_above = cum - histM[bb]; s_found = 1;
                    break;
                }
            }
        }
        __syncthreads();
        const unsigned bT = s_binT;
        for (int p = tid; p < PRI; p += 256) {
            unsigned bits = col[(size_t)p * NCLS_TOT];
            if (__uint_as_float(bits) > CONF_TH && (bits >> 20) >= bT) {
                unsigned pos = atomicAdd(&s_gc, 1u);
                if (pos < CAND_MAX)
                    buf[pos] = ((unsigned long long)bits << 32) | (unsigned)(~(unsigned)p);
            }
        }
        __syncthreads();
        gcount = (int)min(s_gc, (unsigned)CAND_MAX);
        histM[tid] = 0;
        __syncthreads();
    }

    const int found = s_found;
    const unsigned binT = s_binT;
    const unsigned need = KTOP - s_above;

    // ---- fine refinement: bits[19:12] within cut bin ----
    if (found) {
        for (int t = tid; t < gcount; t += 256) {
            unsigned long long key = buf[t];
            if ((unsigned)(key >> 52) == binT)
                atomicAdd(&histM[(unsigned)(key >> 44) & 0xFFu], 1u);
        }
        __syncthreads();
        unsigned part = histM[tid];
        unsigned incl = suffix_incl_256(part, warpTot, lane, wid);
        unsigned excl = incl - part;
        if (excl < need && incl >= need) {
            s_fcut = (unsigned)tid; s_aboveF = excl; s_cntF = part;
        }
        __syncthreads();
    }
    const unsigned fcut = s_fcut;

    // ---- optional fine2 on bits[11:4] (cut-bin overflow only) ----
    if (found && (s_aboveF + s_cntF > CAND2)) {
        const unsigned need2 = need - s_aboveF;
        histM[tid] = 0;
        __syncthreads();
        for (int t = tid; t < gcount; t += 256) {
            unsigned long long key = buf[t];
            if ((unsigned)(key >> 52) == binT &&
                ((unsigned)(key >> 44) & 0xFFu) == fcut)
                atomicAdd(&histM[(unsigned)(key >> 36) & 0xFFu], 1u);
        }
        __syncthreads();
        unsigned part = histM[tid];
        unsigned incl = suffix_incl_256(part, warpTot, lane, wid);
        unsigned excl = incl - part;
        if (excl < need2 && incl >= need2) s_f2cut = (unsigned)tid;
        __syncthreads();
    }
    const unsigned f2cut = s_f2cut;
    __syncthreads();

    // ---- compact refined candidates into cand2 ----
    cand2[tid] = 0ULL;
    __syncthreads();
    for (int t = tid; t < gcount; t += 256) {
        unsigned long long key = buf[t];
        unsigned cb = (unsigned)(key >> 52);
        unsigned fb = (unsigned)(key >> 44) & 0xFFu;
        unsigned f2 = (unsigned)(key >> 36) & 0xFFu;
        if (cb > binT ||
            (cb == binT && (fb > fcut || (fb == fcut && f2 >= f2cut)))) {
            unsigned pos = atomicAdd(&s_n2, 1u);
            if (pos < CAND2) cand2[pos] = key;
        }
    }
    __syncthreads();
    const int n = min((int)min(s_n2, (unsigned)CAND2), KTOP);

    // ---- register bitonic sort (asc) ----
    unsigned long long key = cand2[tid];
    for (int kk = 2; kk <= 256; kk <<= 1) {
        bool up = ((tid & kk) == 0);
        for (int jj = kk >> 1; jj > 0; jj >>= 1) {
            unsigned long long partner;
            if (jj >= 32) {
                __syncthreads();
                cand2[tid] = key;
                __syncthreads();
                partner = cand2[tid ^ jj];
            } else {
                partner = __shfl_xor_sync(0xFFFFFFFFu, key, jj);
            }
            bool takeMin = (((tid & jj) == 0) == up);
            bool sw = takeMin ? (partner < key) : (partner > key);
            if (sw) key = partner;
        }
    }
    __syncthreads();

    // ---- extract top-n (descending) ; zero mask rows [0, n) ----
    {
        int k = 255 - tid;
        if (k < n) {
            unsigned bits = (unsigned)(key >> 32);
            int p = (int)(~(unsigned)key);
            float4 bx = g_boxes[b * PRI + p];
            sBox[k]   = bx;
            sScore[k] = __uint_as_float(bits);
            sTArea[k] = NMS_TH * (bx.z - bx.x) * (bx.w - bx.y);
        }
        for (int t = tid; t < n * 8; t += 256) maskW[t] = 0u;
    }
    __syncthreads();

    // ---- suppression bitmask via ballot; fma-minimized IoU test ----
    const int wEnd = (n + 31) >> 5;
    const float Tp1 = 1.0f + NMS_TH;
    for (int i = wid; i < n; i += 8) {
        float4 bi = sBox[i];
        float  Tai = sTArea[i];
        for (int w = (i + 1) >> 5; w < wEnd; w++) {
            int j = w * 32 + lane;
            bool sup = false;
            if (j > i && j < n) {
                float4 bj = sBox[j];
                float ww = fminf(bi.z, bj.z) - fmaxf(bi.x, bj.x);
                float hh = fminf(bi.w, bj.w) - fmaxf(bi.y, bj.y);
                ww = fmaxf(ww, 0.0f); hh = fmaxf(hh, 0.0f);
                float inter = ww * hh;
                // inter > T*(ai+aj-inter)  <=>  inter*(1+T) > T*ai + T*aj
                sup = fmaf(inter, Tp1, -(Tai + sTArea[j])) > 0.0f;
            }
            unsigned bal = __ballot_sync(0xFFFFFFFFu, sup);
            if (lane == 0) maskW[i * 8 + w] = bal;
        }
    }
    __syncthreads();

    // ---- greedy scan: iterate only over live (kept) boxes via ffs ----
    if (tid == 0) {
        const unsigned long long* m64 = (const unsigned long long*)maskW;
        unsigned long long kw[4];
        #pragma unroll
        for (int q = 0; q < 4; q++) {
            int rem = n - q * 64;
            kw[q] = (rem >= 64) ? ~0ULL : (rem > 0 ? ((1ULL << rem) - 1ULL) : 0ULL);
        }
        #pragma unroll
        for (int q = 0; q < 4; q++) {
            unsigned long long w = kw[q];
            while (w) {
                int bit = __ffsll((long long)w) - 1;
                int i = q * 64 + bit;
                kw[0] &= ~m64[i * 4 + 0]; kw[1] &= ~m64[i * 4 + 1];
                kw[2] &= ~m64[i * 4 + 2]; kw[3] &= ~m64[i * 4 + 3];
                unsigned long long hi = (bit == 63) ? 0ULL : (~0ULL << (bit + 1));
                w = kw[q] & hi;          // mask rows never clear their own bit
            }
        }
        sKeepW[0] = kw[0]; sKeepW[1] = kw[1]; sKeepW[2] = kw[2]; sKeepW[3] = kw[3];
    }
    __syncthreads();

    // ---- write slab ----
    float* outBase = out + (size_t)(b * NCLS_TOT + cc + 1) * KTOP * 5;
    float4* outBase4 = (float4*)outBase;
    for (int t = tid; t < KTOP * 5 / 4; t += 256)
        outBase4[t] = make_float4(0.f, 0.f, 0.f, 0.f);
    __syncthreads();

    for (int k = tid; k < n; k += 256) {
        unsigned long long w = sKeepW[k >> 6];
        if ((w >> (k & 63)) & 1ULL) {
            int d = 0;
            for (int q = 0; q < (k >> 6); q++) d += __popcll(sKeepW[q]);
            unsigned long long below = (k & 63) ? (w & ((1ULL << (k & 63)) - 1ULL)) : 0ULL;
            d += __popcll(below);
            float* r = outBase + d * 5;
            float4 bx = sBox[k];
            r[0] = sScore[k];
            r[1] = bx.x; r[2] = bx.y; r[3] = bx.z; r[4] = bx.w;
        }
    }
}

// ---------------------------------------------------------------------------
extern "C" void kernel_launch(void* const* d_in, const int* in_sizes, int n_in,
                              void* d_out, int out_size) {
    const float4*   loc   = (const float4*)d_in[0];     // [B, P, 4]
    const unsigned* conf  = (const unsigned*)d_in[1];   // [B*P, C] (float bits)
    const float4*   prior = (const float4*)d_in[2];     // [P, 4]
    float* out = (float*)d_out;                         // [B, C, K, 5]

    decode_kernel<<<(BATCH * PRI + 255) / 256, 256>>>(loc, prior);
    zero_misc_kernel<<<(BATCH * KTOP * 5 + 255) / 256, 256>>>(out);

    dim3 fg(NCHUNK, BATCH);
    filter_kernel<<<fg, 256>>>(conf);

    nms_kernel<<<NTASK, 256>>>(conf, out);
}